// round 2
// baseline (speedup 1.0000x reference)
#include <cuda_runtime.h>
#include <mma.h>
#include <math.h>

using namespace nvcuda;

// Problem constants
#define BB   2
#define SS   2048
#define HH   2048
#define NH   16
#define DD   128
#define MM   (BB*SS)       // 4096 rows

// Scratch (device globals — no allocation allowed)
__device__ float g_q[(size_t)MM*HH];
__device__ float g_k[(size_t)MM*HH];
__device__ float g_v[(size_t)MM*HH];
__device__ float g_ctx[(size_t)MM*HH];
__device__ float g_cos[SS*64];
__device__ float g_sin[SS*64];

// ---------------------------------------------------------------------------
// RoPE tables: match reference fp32 semantics (invf in fp32, angle = fl32(s*invf)),
// but evaluate pow/cos in double so we agree with CPU libm to ~1 ulp.
// ---------------------------------------------------------------------------
__global__ void rope_tables_kernel() {
    int t = blockIdx.x * blockDim.x + threadIdx.x;
    if (t >= SS * 64) return;
    int i = t & 63;
    int s = t >> 6;
    double invf_d = pow(10000.0, -((double)(2 * i) / 128.0));
    float invf = (float)invf_d;
    float ang = (float)s * invf;        // fp32 product, same as reference
    double a = (double)ang;
    g_cos[t] = (float)cos(a);
    g_sin[t] = (float)sin(a);
}

// ---------------------------------------------------------------------------
// In-place RoPE on a [MM, HH] buffer laid out (b*S+s, h*128+d)
// ---------------------------------------------------------------------------
__global__ void rope_apply_kernel(float* __restrict__ buf) {
    int t = blockIdx.x * blockDim.x + threadIdx.x;
    const int total = MM * NH * 64;
    if (t >= total) return;
    int d   = t & 63;
    int h   = (t >> 6) & (NH - 1);
    int row = t >> 10;
    int s   = row & (SS - 1);
    float c  = g_cos[(s << 6) + d];
    float sn = g_sin[(s << 6) + d];
    size_t idx = (size_t)row * HH + (h << 7) + d;
    float x1 = buf[idx];
    float x2 = buf[idx + 64];
    buf[idx]      = x1 * c - x2 * sn;
    buf[idx + 64] = x2 * c + x1 * sn;
}

// ---------------------------------------------------------------------------
// NT GEMM, 3xTF32 (hi/lo split) for fp32-class precision.
// C[M,N] = A[M,K] * B[N,K]^T  (all row-major)
// Block 128x128, K-step 32, 8 warps, warp tile 64x32.
// ---------------------------------------------------------------------------
#define GLD 40   // smem leading dim (floats): 160B, multiple of 32B

__global__ __launch_bounds__(256) void gemm_nt_3xtf32(
    const float* __restrict__ A, const float* __restrict__ Bm,
    float* __restrict__ C, int Md, int Nd, int Kd)
{
    __shared__ __align__(32) float As[128 * GLD];
    __shared__ __align__(32) float Bs[128 * GLD];

    const int tid = threadIdx.x;
    const int w   = tid >> 5;
    const int wm  = w >> 2;   // 0..1  (64 rows each)
    const int wn  = w & 3;    // 0..3  (32 cols each)
    const int bm  = blockIdx.y * 128;
    const int bn  = blockIdx.x * 128;

    wmma::fragment<wmma::accumulator, 16, 16, 8, float> acc[4][2];
    #pragma unroll
    for (int i = 0; i < 4; i++)
        #pragma unroll
        for (int j = 0; j < 2; j++)
            wmma::fill_fragment(acc[i][j], 0.0f);

    for (int k0 = 0; k0 < Kd; k0 += 32) {
        #pragma unroll
        for (int l = tid; l < 128 * 8; l += 256) {
            int m  = l >> 3;
            int k4 = l & 7;
            *(float4*)&As[m * GLD + k4 * 4] =
                *(const float4*)&A[(size_t)(bm + m) * Kd + k0 + k4 * 4];
            *(float4*)&Bs[m * GLD + k4 * 4] =
                *(const float4*)&Bm[(size_t)(bn + m) * Kd + k0 + k4 * 4];
        }
        __syncthreads();

        #pragma unroll
        for (int kk = 0; kk < 4; kk++) {
            wmma::fragment<wmma::matrix_a, 16, 16, 8, wmma::precision::tf32, wmma::row_major> a_hi[4], a_lo[4];
            wmma::fragment<wmma::matrix_b, 16, 16, 8, wmma::precision::tf32, wmma::col_major> b_hi[2], b_lo[2];

            #pragma unroll
            for (int i = 0; i < 4; i++) {
                wmma::load_matrix_sync(a_hi[i], As + (wm * 64 + i * 16) * GLD + kk * 8, GLD);
                #pragma unroll
                for (int e = 0; e < a_hi[i].num_elements; e++) {
                    float v  = a_hi[i].x[e];
                    float hv = wmma::__float_to_tf32(v);
                    a_hi[i].x[e] = hv;
                    a_lo[i].x[e] = wmma::__float_to_tf32(v - hv);
                }
            }
            #pragma unroll
            for (int j = 0; j < 2; j++) {
                wmma::load_matrix_sync(b_hi[j], Bs + (wn * 32 + j * 16) * GLD + kk * 8, GLD);
                #pragma unroll
                for (int e = 0; e < b_hi[j].num_elements; e++) {
                    float v  = b_hi[j].x[e];
                    float hv = wmma::__float_to_tf32(v);
                    b_hi[j].x[e] = hv;
                    b_lo[j].x[e] = wmma::__float_to_tf32(v - hv);
                }
            }
            #pragma unroll
            for (int i = 0; i < 4; i++)
                #pragma unroll
                for (int j = 0; j < 2; j++) {
                    wmma::mma_sync(acc[i][j], a_hi[i], b_hi[j], acc[i][j]);
                    wmma::mma_sync(acc[i][j], a_lo[i], b_hi[j], acc[i][j]);
                    wmma::mma_sync(acc[i][j], a_hi[i], b_lo[j], acc[i][j]);
                }
        }
        __syncthreads();
    }

    #pragma unroll
    for (int i = 0; i < 4; i++)
        #pragma unroll
        for (int j = 0; j < 2; j++)
            wmma::store_matrix_sync(
                C + (size_t)(bm + wm * 64 + i * 16) * Nd + bn + wn * 32 + j * 16,
                acc[i][j], Nd, wmma::mem_row_major);
}

// ---------------------------------------------------------------------------
// Flash attention (causal), per block: one (b, h, 64-row q-tile).
// scores: 3xTF32 (precision-critical near softmax ties); P*V: single-pass tf32.
// O accumulator kept as explicit per-thread registers (known mapping) via a
// smem round-trip of the P*V tile — no reliance on accumulator frag layout.
// ---------------------------------------------------------------------------
#define ATT_LD 136   // 544B rows, 32B-aligned sub-tiles
#define PS_LD  72    // 288B rows

#define ATT_SMEM ((3 * 64 * ATT_LD + 64 * PS_LD) * 4)

__global__ __launch_bounds__(256) void attn_kernel() {
    const int qt = (int)gridDim.x - 1 - (int)blockIdx.x;  // heavy tiles first
    const int h  = blockIdx.y;
    const int b  = blockIdx.z;

    extern __shared__ __align__(32) float sm[];
    float* Qs = sm;
    float* Ks = Qs + 64 * ATT_LD;   // doubles as the P*V result buffer
    float* Vs = Ks + 64 * ATT_LD;
    float* Ps = Vs + 64 * ATT_LD;

    const int tid  = threadIdx.x;
    const int w    = tid >> 5;
    const int wm   = w >> 1;   // 0..3 (16 q-rows each)
    const int wn   = w & 1;    // 0..1

    const float* qp = g_q + (size_t)b * SS * HH + (size_t)h * DD;
    const float* kp = g_k + (size_t)b * SS * HH + (size_t)h * DD;
    const float* vp = g_v + (size_t)b * SS * HH + (size_t)h * DD;

    // Load Q tile (resident for whole block)
    for (int l = tid; l < 64 * 32; l += 256) {
        int rr = l >> 5, c4 = l & 31;
        *(float4*)&Qs[rr * ATT_LD + c4 * 4] =
            *(const float4*)&qp[(size_t)(qt * 64 + rr) * HH + c4 * 4];
    }

    const int r    = tid >> 2;   // softmax/O row owned by this thread (4 thr/row)
    const int sub  = tid & 3;
    const int qglob = qt * 64 + r;
    const float SCALE = sqrtf(128.0f);

    float row_m = -INFINITY;
    float row_l = 0.0f;
    float o[32];
    #pragma unroll
    for (int i = 0; i < 32; i++) o[i] = 0.0f;

    for (int kt = 0; kt <= qt; ++kt) {
        const int kbase = kt * 64;
        __syncthreads();  // prior O-update reads of Ks done before overwrite

        for (int l = tid; l < 64 * 32; l += 256) {
            int rr = l >> 5, c4 = l & 31;
            size_t g = (size_t)(kbase + rr) * HH + c4 * 4;
            *(float4*)&Ks[rr * ATT_LD + c4 * 4] = *(const float4*)&kp[g];
            *(float4*)&Vs[rr * ATT_LD + c4 * 4] = *(const float4*)&vp[g];
        }
        __syncthreads();

        // ---- scores = Q * K^T (3xTF32), warp tile 16x32 ----
        {
            wmma::fragment<wmma::accumulator, 16, 16, 8, float> sacc[2];
            wmma::fill_fragment(sacc[0], 0.0f);
            wmma::fill_fragment(sacc[1], 0.0f);
            #pragma unroll
            for (int ks = 0; ks < 16; ks++) {
                wmma::fragment<wmma::matrix_a, 16, 16, 8, wmma::precision::tf32, wmma::row_major> a_hi, a_lo;
                wmma::load_matrix_sync(a_hi, Qs + (wm * 16) * ATT_LD + ks * 8, ATT_LD);
                #pragma unroll
                for (int e = 0; e < a_hi.num_elements; e++) {
                    float vv = a_hi.x[e];
                    float hv = wmma::__float_to_tf32(vv);
                    a_hi.x[e] = hv;
                    a_lo.x[e] = wmma::__float_to_tf32(vv - hv);
                }
                #pragma unroll
                for (int j = 0; j < 2; j++) {
                    wmma::fragment<wmma::matrix_b, 16, 16, 8, wmma::precision::tf32, wmma::col_major> b_hi, b_lo;
                    wmma::load_matrix_sync(b_hi, Ks + (wn * 32 + j * 16) * ATT_LD + ks * 8, ATT_LD);
                    #pragma unroll
                    for (int e = 0; e < b_hi.num_elements; e++) {
                        float vv = b_hi.x[e];
                        float hv = wmma::__float_to_tf32(vv);
                        b_hi.x[e] = hv;
                        b_lo.x[e] = wmma::__float_to_tf32(vv - hv);
                    }
                    wmma::mma_sync(sacc[j], a_hi, b_hi, sacc[j]);
                    wmma::mma_sync(sacc[j], a_lo, b_hi, sacc[j]);
                    wmma::mma_sync(sacc[j], a_hi, b_lo, sacc[j]);
                }
            }
            #pragma unroll
            for (int j = 0; j < 2; j++)
                wmma::store_matrix_sync(Ps + (wm * 16) * PS_LD + wn * 32 + j * 16,
                                        sacc[j], PS_LD, wmma::mem_row_major);
        }
        __syncthreads();

        // ---- online softmax (4 threads per row, 16 cols each) ----
        float alpha;
        {
            float vals[16];
            float tmax = -INFINITY;
            #pragma unroll
            for (int c0 = 0; c0 < 16; c0++) {
                int c = sub * 16 + c0;
                float sc = Ps[r * PS_LD + c] * SCALE;
                if (kbase + c > qglob) sc = -INFINITY;
                vals[c0] = sc;
                tmax = fmaxf(tmax, sc);
            }
            tmax = fmaxf(tmax, __shfl_xor_sync(0xffffffffu, tmax, 1));
            tmax = fmaxf(tmax, __shfl_xor_sync(0xffffffffu, tmax, 2));
            float newm = fmaxf(row_m, tmax);
            float lsum = 0.0f;
            #pragma unroll
            for (int c0 = 0; c0 < 16; c0++) {
                float p = __expf(vals[c0] - newm);
                Ps[r * PS_LD + sub * 16 + c0] = p;
                lsum += p;
            }
            lsum += __shfl_xor_sync(0xffffffffu, lsum, 1);
            lsum += __shfl_xor_sync(0xffffffffu, lsum, 2);
            alpha = __expf(row_m - newm);
            row_l = row_l * alpha + lsum;
            row_m = newm;
        }
        __syncthreads();

        // ---- O_tile = P * V (single-pass tf32), warp tile 16x64 ----
        {
            wmma::fragment<wmma::accumulator, 16, 16, 8, float> oac[4];
            #pragma unroll
            for (int j = 0; j < 4; j++) wmma::fill_fragment(oac[j], 0.0f);
            #pragma unroll
            for (int ks = 0; ks < 8; ks++) {
                wmma::fragment<wmma::matrix_a, 16, 16, 8, wmma::precision::tf32, wmma::row_major> pa;
                wmma::load_matrix_sync(pa, Ps + (wm * 16) * PS_LD + ks * 8, PS_LD);
                #pragma unroll
                for (int e = 0; e < pa.num_elements; e++)
                    pa.x[e] = wmma::__float_to_tf32(pa.x[e]);
                #pragma unroll
                for (int j = 0; j < 4; j++) {
                    wmma::fragment<wmma::matrix_b, 16, 16, 8, wmma::precision::tf32, wmma::row_major> vb;
                    wmma::load_matrix_sync(vb, Vs + (ks * 8) * ATT_LD + wn * 64 + j * 16, ATT_LD);
                    #pragma unroll
                    for (int e = 0; e < vb.num_elements; e++)
                        vb.x[e] = wmma::__float_to_tf32(vb.x[e]);
                    wmma::mma_sync(oac[j], pa, vb, oac[j]);
                }
            }
            #pragma unroll
            for (int j = 0; j < 4; j++)
                wmma::store_matrix_sync(Ks + (wm * 16) * ATT_LD + wn * 64 + j * 16,
                                        oac[j], ATT_LD, wmma::mem_row_major);
        }
        __syncthreads();

        // ---- O register update (interleaved cols: sub + 4*i, conflict-lite) ----
        #pragma unroll
        for (int i = 0; i < 32; i++)
            o[i] = o[i] * alpha + Ks[r * ATT_LD + sub + 4 * i];
    }

    // ---- write ctx ----
    float inv = 1.0f / row_l;
    float* cp = g_ctx + (size_t)(b * SS + qglob) * HH + (size_t)h * DD;
    #pragma unroll
    for (int i = 0; i < 32; i++)
        cp[sub + 4 * i] = o[i] * inv;
}

// ---------------------------------------------------------------------------
// Launch
// ---------------------------------------------------------------------------
extern "C" void kernel_launch(void* const* d_in, const int* in_sizes, int n_in,
                              void* d_out, int out_size) {
    const float* x  = (const float*)d_in[0];
    const float* Wq = (const float*)d_in[1];
    const float* Wk = (const float*)d_in[2];
    const float* Wv = (const float*)d_in[3];
    const float* Wo = (const float*)d_in[4];
    float* out = (float*)d_out;

    float *q, *k, *v, *ctx;
    cudaGetSymbolAddress((void**)&q,   g_q);
    cudaGetSymbolAddress((void**)&k,   g_k);
    cudaGetSymbolAddress((void**)&v,   g_v);
    cudaGetSymbolAddress((void**)&ctx, g_ctx);

    cudaFuncSetAttribute(attn_kernel,
                         cudaFuncAttributeMaxDynamicSharedMemorySize, ATT_SMEM);

    rope_tables_kernel<<<(SS * 64 + 255) / 256, 256>>>();

    dim3 ggrid(HH / 128, MM / 128);  // (16, 32)
    gemm_nt_3xtf32<<<ggrid, 256>>>(x, Wq, q, MM, HH, HH);
    gemm_nt_3xtf32<<<ggrid, 256>>>(x, Wk, k, MM, HH, HH);
    gemm_nt_3xtf32<<<ggrid, 256>>>(x, Wv, v, MM, HH, HH);

    int rt = MM * NH * 64;
    rope_apply_kernel<<<rt / 256, 256>>>(q);
    rope_apply_kernel<<<rt / 256, 256>>>(k);

    attn_kernel<<<dim3(SS / 64, NH, BB), 256, ATT_SMEM>>>();

    gemm_nt_3xtf32<<<ggrid, 256>>>(ctx, Wo, out, MM, HH, HH);
}